// round 1
// baseline (speedup 1.0000x reference)
#include <cuda_runtime.h>
#include <cstring>

#define TLEN   4096
#define DMODEL 1024
#define NHEADS 16
#define HDIM   64

// ---------------- scratch (device globals: allocation-free) ----------------
__device__ float g_q[NHEADS * TLEN * HDIM];  // [h][t][d]
__device__ float g_k[NHEADS * TLEN * HDIM];  // [h][s][d]
__device__ float g_v[NHEADS * TLEN * HDIM];  // [h][s][d]
__device__ float g_o[TLEN * DMODEL];         // [t][h*64+d]

// ---------------- fastexp_gist: exact Schraudolph semantics ----------------
__device__ __forceinline__ float fastexp_g(float x) {
    const float GA = (float)12102203.17133801;
    const float GB = (float)1064986823.010288;
    const float GC = 8388608.0f;
    const float GD = 2139095040.0f;
    // separate mul + add (no FMA contraction) to match reference fp32 ops
    float y = __fadd_rn(__fmul_rn(GA, x), GB);
    int yi = (y < GC || y > GD) ? 0 : __float2int_rz(y);
    return __int_as_float(yi);
}

// ============================================================================
// Projection GEMM: C[4096,1024] = A[4096,1024] @ W[1024,1024]^T (+bias)
// 128x128 block tile, BK=8, 256 threads, 8x8 per thread.
// c_sel: 0->g_q, 1->g_k, 2->g_v (head-major scatter), 3->dout (row-major)
// a_sel: 0->Ain param, 1->g_o
// ============================================================================
__global__ __launch_bounds__(256)
void proj_kernel(const float* __restrict__ Ain, const float* __restrict__ W,
                 const float* __restrict__ bias, float* __restrict__ dout,
                 int a_sel, int c_sel)
{
    const float* A = a_sel ? (const float*)g_o : Ain;
    float* C = (c_sel == 0) ? g_q : (c_sel == 1) ? g_k : (c_sel == 2) ? g_v : dout;

    __shared__ float As[8][128];
    __shared__ float Bs[8][128];

    const int tid = threadIdx.x;
    const int tx = tid & 15;          // 0..15 -> n
    const int ty = tid >> 4;          // 0..15 -> m
    const int m0 = blockIdx.y * 128;
    const int n0 = blockIdx.x * 128;

    const int lrow = tid >> 1;        // 0..127
    const int lk   = (tid & 1) * 4;   // 0 or 4

    const float* Ap = A + (size_t)(m0 + lrow) * DMODEL + lk;
    const float* Wp = W + (size_t)(n0 + lrow) * DMODEL + lk;

    float acc[8][8];
    #pragma unroll
    for (int i = 0; i < 8; i++)
        #pragma unroll
        for (int j = 0; j < 8; j++) acc[i][j] = 0.f;

    for (int k0 = 0; k0 < DMODEL; k0 += 8) {
        float4 av = *(const float4*)(Ap + k0);
        float4 wv = *(const float4*)(Wp + k0);
        __syncthreads();
        As[lk + 0][lrow] = av.x; As[lk + 1][lrow] = av.y;
        As[lk + 2][lrow] = av.z; As[lk + 3][lrow] = av.w;
        Bs[lk + 0][lrow] = wv.x; Bs[lk + 1][lrow] = wv.y;
        Bs[lk + 2][lrow] = wv.z; Bs[lk + 3][lrow] = wv.w;
        __syncthreads();
        #pragma unroll
        for (int kk = 0; kk < 8; kk++) {
            float a[8], b[8];
            *(float4*)(a)     = *(const float4*)(&As[kk][ty * 8]);
            *(float4*)(a + 4) = *(const float4*)(&As[kk][ty * 8 + 4]);
            *(float4*)(b)     = *(const float4*)(&Bs[kk][tx * 8]);
            *(float4*)(b + 4) = *(const float4*)(&Bs[kk][tx * 8 + 4]);
            #pragma unroll
            for (int i = 0; i < 8; i++)
                #pragma unroll
                for (int j = 0; j < 8; j++)
                    acc[i][j] = fmaf(a[i], b[j], acc[i][j]);
        }
    }

    float bb[8];
    #pragma unroll
    for (int j = 0; j < 8; j++)
        bb[j] = bias ? bias[n0 + tx * 8 + j] : 0.f;

    const bool head_major = (c_sel <= 2);
    #pragma unroll
    for (int i = 0; i < 8; i++) {
        int m = m0 + ty * 8 + i;
        #pragma unroll
        for (int jg = 0; jg < 8; jg += 4) {
            int n = n0 + tx * 8 + jg;
            float4 r;
            r.x = acc[i][jg + 0] + bb[jg + 0];
            r.y = acc[i][jg + 1] + bb[jg + 1];
            r.z = acc[i][jg + 2] + bb[jg + 2];
            r.w = acc[i][jg + 3] + bb[jg + 3];
            float* dst;
            if (head_major) {
                int hh = n >> 6, dd = n & 63;
                dst = C + ((size_t)hh * TLEN + m) * HDIM + dd;
            } else {
                dst = C + (size_t)m * DMODEL + n;
            }
            *(float4*)dst = r;
        }
    }
}

// ============================================================================
// Fused attention: per (head, 64-row Q block).
// Pass 1: row max of scaled scores (streamed over K tiles).
// Pass 2: recompute scores, e = fastexp(s*scale - max), accumulate sum and E@V.
// XOR swizzle at float4 granularity keeps inner-loop LDS.128 conflict-free.
// ============================================================================
#define SW(row, col) (((row) << 6) + (((((col) >> 2) ^ ((row) & 15))) << 2) + ((col) & 3))

#define ATTN_SMEM_FLOATS (4 * 4096 + 128)
#define ATTN_SMEM_BYTES  (ATTN_SMEM_FLOATS * 4)

__global__ __launch_bounds__(256)
void attn_kernel(float scaling)
{
    extern __shared__ float sm[];
    float* QsT    = sm;            // [d][m] swizzled, 4096
    float* KsT    = sm + 4096;     // [d][s] swizzled
    float* Vs     = sm + 8192;     // [s][d] swizzled
    float* EsT    = sm + 12288;    // [s][m] swizzled (also reduction scratch)
    float* rowmax = sm + 16384;    // 64
    float* rowsum = sm + 16448;    // 64

    const int tid = threadIdx.x;
    const int tx = tid & 15;       // -> s / dv columns (4 each)
    const int ty = tid >> 4;       // -> m rows (4 each)
    const int h  = blockIdx.y;
    const int t0 = blockIdx.x * 64;

    const float* Qg = g_q + ((size_t)h * TLEN + t0) * HDIM;
    const float* Kg = g_k + (size_t)h * TLEN * HDIM;
    const float* Vg = g_v + (size_t)h * TLEN * HDIM;

    // ---- load Q tile, transposed [d][m] ----
    #pragma unroll
    for (int p = 0; p < 4; p++) {
        int f = p * 256 + tid;
        int m = f >> 4;
        int d0 = (f & 15) << 2;
        float4 q4 = *(const float4*)(Qg + (size_t)m * HDIM + d0);
        QsT[SW(d0 + 0, m)] = q4.x;
        QsT[SW(d0 + 1, m)] = q4.y;
        QsT[SW(d0 + 2, m)] = q4.z;
        QsT[SW(d0 + 3, m)] = q4.w;
    }

    const float NEG = -3.402823466e38f;
    float rmax[4] = {NEG, NEG, NEG, NEG};

    // ======================= pass 1: row max =======================
    for (int st = 0; st < TLEN / 64; st++) {
        __syncthreads();
        #pragma unroll
        for (int p = 0; p < 4; p++) {
            int f = p * 256 + tid;
            int s = f >> 4;
            int d0 = (f & 15) << 2;
            float4 k4 = *(const float4*)(Kg + (size_t)(st * 64 + s) * HDIM + d0);
            KsT[SW(d0 + 0, s)] = k4.x;
            KsT[SW(d0 + 1, s)] = k4.y;
            KsT[SW(d0 + 2, s)] = k4.z;
            KsT[SW(d0 + 3, s)] = k4.w;
        }
        __syncthreads();

        float sacc[4][4];
        #pragma unroll
        for (int i = 0; i < 4; i++)
            #pragma unroll
            for (int j = 0; j < 4; j++) sacc[i][j] = 0.f;

        #pragma unroll 16
        for (int k = 0; k < 64; k++) {
            float a[4], b[4];
            *(float4*)a = *(const float4*)(&QsT[(k << 6) + ((ty ^ (k & 15)) << 2)]);
            *(float4*)b = *(const float4*)(&KsT[(k << 6) + ((tx ^ (k & 15)) << 2)]);
            #pragma unroll
            for (int i = 0; i < 4; i++)
                #pragma unroll
                for (int j = 0; j < 4; j++)
                    sacc[i][j] = fmaf(a[i], b[j], sacc[i][j]);
        }
        #pragma unroll
        for (int i = 0; i < 4; i++)
            #pragma unroll
            for (int j = 0; j < 4; j++)
                rmax[i] = fmaxf(rmax[i], __fmul_rn(sacc[i][j], scaling));
    }

    // ---- reduce row max across tx (EsT reused as scratch) ----
    __syncthreads();
    #pragma unroll
    for (int i = 0; i < 4; i++)
        EsT[(4 * ty + i) * 16 + tx] = rmax[i];
    __syncthreads();
    if (tid < 64) {
        float mv = EsT[tid * 16];
        #pragma unroll
        for (int q = 1; q < 16; q++) mv = fmaxf(mv, EsT[tid * 16 + q]);
        rowmax[tid] = mv;
    }
    __syncthreads();
    float rm[4];
    #pragma unroll
    for (int i = 0; i < 4; i++) rm[i] = rowmax[4 * ty + i];

    // ======================= pass 2: exp-sum + E@V =======================
    float oacc[4][4];
    float rsum[4] = {0.f, 0.f, 0.f, 0.f};
    #pragma unroll
    for (int i = 0; i < 4; i++)
        #pragma unroll
        for (int j = 0; j < 4; j++) oacc[i][j] = 0.f;

    for (int st = 0; st < TLEN / 64; st++) {
        __syncthreads();
        #pragma unroll
        for (int p = 0; p < 4; p++) {
            int f = p * 256 + tid;
            int s = f >> 4;
            int d0 = (f & 15) << 2;
            float4 k4 = *(const float4*)(Kg + (size_t)(st * 64 + s) * HDIM + d0);
            KsT[SW(d0 + 0, s)] = k4.x;
            KsT[SW(d0 + 1, s)] = k4.y;
            KsT[SW(d0 + 2, s)] = k4.z;
            KsT[SW(d0 + 3, s)] = k4.w;
        }
        #pragma unroll
        for (int p = 0; p < 4; p++) {
            int f = p * 256 + tid;
            int s = f >> 4;
            int c = f & 15;
            float4 v4 = *(const float4*)(Vg + (size_t)(st * 64 + s) * HDIM + (c << 2));
            *(float4*)(&Vs[(s << 6) + ((c ^ (s & 15)) << 2)]) = v4;
        }
        __syncthreads();

        float sacc[4][4];
        #pragma unroll
        for (int i = 0; i < 4; i++)
            #pragma unroll
            for (int j = 0; j < 4; j++) sacc[i][j] = 0.f;

        #pragma unroll 16
        for (int k = 0; k < 64; k++) {
            float a[4], b[4];
            *(float4*)a = *(const float4*)(&QsT[(k << 6) + ((ty ^ (k & 15)) << 2)]);
            *(float4*)b = *(const float4*)(&KsT[(k << 6) + ((tx ^ (k & 15)) << 2)]);
            #pragma unroll
            for (int i = 0; i < 4; i++)
                #pragma unroll
                for (int j = 0; j < 4; j++)
                    sacc[i][j] = fmaf(a[i], b[j], sacc[i][j]);
        }

        // e = fastexp(scaled - rowmax); write E^T to smem; accumulate sums
        #pragma unroll
        for (int i = 0; i < 4; i++) {
            #pragma unroll
            for (int j = 0; j < 4; j++) {
                float sc = __fmul_rn(sacc[i][j], scaling);
                float e = fastexp_g(sc - rm[i]);
                rsum[i] += e;
                int s = 4 * tx + j;
                EsT[(s << 6) + ((ty ^ (s & 15)) << 2) + i] = e;
            }
        }
        __syncthreads();

        // O += E^T' @ V  (k = local s)
        #pragma unroll 16
        for (int k = 0; k < 64; k++) {
            float a[4], b[4];
            *(float4*)a = *(const float4*)(&EsT[(k << 6) + ((ty ^ (k & 15)) << 2)]);
            *(float4*)b = *(const float4*)(&Vs[(k << 6) + ((tx ^ (k & 15)) << 2)]);
            #pragma unroll
            for (int i = 0; i < 4; i++)
                #pragma unroll
                for (int j = 0; j < 4; j++)
                    oacc[i][j] = fmaf(a[i], b[j], oacc[i][j]);
        }
    }

    // ---- reduce row sums across tx ----
    __syncthreads();
    #pragma unroll
    for (int i = 0; i < 4; i++)
        EsT[(4 * ty + i) * 16 + tx] = rsum[i];
    __syncthreads();
    if (tid < 64) {
        float sv = 0.f;
        #pragma unroll
        for (int q = 0; q < 16; q++) sv += EsT[tid * 16 + q];
        rowsum[tid] = sv;
    }
    __syncthreads();

    // ---- normalize + write O[t][h*64+dv] ----
    #pragma unroll
    for (int i = 0; i < 4; i++) {
        int t = t0 + 4 * ty + i;
        float inv = 1.0f / rowsum[4 * ty + i];
        float4 r;
        r.x = oacc[i][0] * inv;
        r.y = oacc[i][1] * inv;
        r.z = oacc[i][2] * inv;
        r.w = oacc[i][3] * inv;
        *(float4*)(&g_o[(size_t)t * DMODEL + h * HDIM + 4 * tx]) = r;
    }
}

// ============================================================================
extern "C" void kernel_launch(void* const* d_in, const int* in_sizes, int n_in,
                              void* d_out, int out_size)
{
    const float* x  = (const float*)d_in[0];
    const float* Wq = (const float*)d_in[1];
    const float* bq = (const float*)d_in[2];
    const float* Wk = (const float*)d_in[3];
    const float* bk = (const float*)d_in[4];
    const float* Wv = (const float*)d_in[5];
    const float* bv = (const float*)d_in[6];
    const float* Wo = (const float*)d_in[7];
    float* out = (float*)d_out;

    // Quake q_rsqrt(HEAD_DIM=64) in exact fp32 step order
    float xq = 64.0f;
    int ib;
    memcpy(&ib, &xq, 4);
    ib = 0x5f3759df - (ib >> 1);
    float y;
    memcpy(&y, &ib, 4);
    float t = 0.5f * xq;
    t = t * y;
    t = t * y;
    float scaling = y * (1.5f - t);

    cudaFuncSetAttribute(attn_kernel, cudaFuncAttributeMaxDynamicSharedMemorySize,
                         ATTN_SMEM_BYTES);

    dim3 pgrid(DMODEL / 128, TLEN / 128);
    proj_kernel<<<pgrid, 256>>>(x, Wq, bq, out, 0, 0);
    proj_kernel<<<pgrid, 256>>>(x, Wk, bk, out, 0, 1);
    proj_kernel<<<pgrid, 256>>>(x, Wv, bv, out, 0, 2);

    attn_kernel<<<dim3(TLEN / 64, NHEADS), 256, ATTN_SMEM_BYTES>>>(scaling);

    proj_kernel<<<pgrid, 256>>>(nullptr, Wo, nullptr, out, 1, 3);
}

// round 2
// speedup vs baseline: 2.6878x; 2.6878x over previous
#include <cuda_runtime.h>
#include <cuda_bf16.h>
#include <cstring>
#include <cstdint>

#define TLEN   4096
#define DMODEL 1024
#define NHEADS 16
#define HDIM   64

// ---------------- device scratch (static: allocation-free) ----------------
__device__ __nv_bfloat16 g_xh[TLEN * DMODEL], g_xl[TLEN * DMODEL];
__device__ __nv_bfloat16 g_wh[4 * DMODEL * DMODEL], g_wl[4 * DMODEL * DMODEL];
__device__ __nv_bfloat16 g_qh[NHEADS * TLEN * HDIM], g_ql[NHEADS * TLEN * HDIM];
__device__ __nv_bfloat16 g_kh[NHEADS * TLEN * HDIM], g_kl[NHEADS * TLEN * HDIM];
__device__ __nv_bfloat16 g_vh[NHEADS * TLEN * HDIM], g_vl[NHEADS * TLEN * HDIM];
__device__ __nv_bfloat16 g_oh[TLEN * DMODEL], g_ol[TLEN * DMODEL];

// ---------------- fastexp_gist: exact Schraudolph semantics ----------------
__device__ __forceinline__ float fastexp_g(float x) {
    const float GA = (float)12102203.17133801;
    const float GB = (float)1064986823.010288;
    const float GC = 8388608.0f;
    const float GD = 2139095040.0f;
    float y = __fadd_rn(__fmul_rn(GA, x), GB);
    int yi = (y < GC || y > GD) ? 0 : __float2int_rz(y);
    return __int_as_float(yi);
}

// ---------------- MMA / LDSM helpers ----------------
__device__ __forceinline__ uint32_t sptr(const char* p) {
    return (uint32_t)__cvta_generic_to_shared(p);
}
__device__ __forceinline__ void ldsm4(uint32_t a, uint32_t& r0, uint32_t& r1,
                                      uint32_t& r2, uint32_t& r3) {
    asm volatile("ldmatrix.sync.aligned.m8n8.x4.shared.b16 {%0,%1,%2,%3}, [%4];"
                 : "=r"(r0), "=r"(r1), "=r"(r2), "=r"(r3) : "r"(a));
}
__device__ __forceinline__ void ldsm4t(uint32_t a, uint32_t& r0, uint32_t& r1,
                                       uint32_t& r2, uint32_t& r3) {
    asm volatile("ldmatrix.sync.aligned.m8n8.x4.trans.shared.b16 {%0,%1,%2,%3}, [%4];"
                 : "=r"(r0), "=r"(r1), "=r"(r2), "=r"(r3) : "r"(a));
}
__device__ __forceinline__ void mma16816(float* c, const uint32_t* a,
                                         uint32_t b0, uint32_t b1) {
    asm volatile(
        "mma.sync.aligned.m16n8k16.row.col.f32.bf16.bf16.f32 "
        "{%0,%1,%2,%3}, {%4,%5,%6,%7}, {%8,%9}, {%0,%1,%2,%3};"
        : "+f"(c[0]), "+f"(c[1]), "+f"(c[2]), "+f"(c[3])
        : "r"(a[0]), "r"(a[1]), "r"(a[2]), "r"(a[3]), "r"(b0), "r"(b1));
}

// byte offset of the 16B chunk (row, ch) in a 64-col bf16 tile (128B rows), swizzled
__device__ __forceinline__ int sw128B(int row, int ch) {
    return (row << 7) + ((ch ^ (row & 7)) << 4);
}
// byte offset in a 128-col bf16 tile (256B rows), swizzled (16 chunks)
__device__ __forceinline__ int sw256B(int row, int ch) {
    return (row << 8) + (((ch & 8) | ((ch & 7) ^ (row & 7))) << 4);
}

__device__ __forceinline__ void split2(float v0, float v1, uint32_t& ph, uint32_t& pl) {
    __nv_bfloat16 h0 = __float2bfloat16(v0), h1 = __float2bfloat16(v1);
    __nv_bfloat16 l0 = __float2bfloat16(v0 - __bfloat162float(h0));
    __nv_bfloat16 l1 = __float2bfloat16(v1 - __bfloat162float(h1));
    ph = (uint32_t)__bfloat16_as_ushort(h0) | ((uint32_t)__bfloat16_as_ushort(h1) << 16);
    pl = (uint32_t)__bfloat16_as_ushort(l0) | ((uint32_t)__bfloat16_as_ushort(l1) << 16);
}

// ---------------- split (fp32 -> bf16 hi/lo planes) ----------------
__global__ void split_kernel(const float* __restrict__ src, int sel, int n) {
    __nv_bfloat16 *hi, *lo;
    switch (sel) {
        case 0:  hi = g_xh; lo = g_xl; break;
        case 1:  hi = g_wh; lo = g_wl; break;
        case 2:  hi = g_wh + 1 * DMODEL * DMODEL; lo = g_wl + 1 * DMODEL * DMODEL; break;
        case 3:  hi = g_wh + 2 * DMODEL * DMODEL; lo = g_wl + 2 * DMODEL * DMODEL; break;
        default: hi = g_wh + 3 * DMODEL * DMODEL; lo = g_wl + 3 * DMODEL * DMODEL; break;
    }
    for (int i = blockIdx.x * blockDim.x + threadIdx.x; i < n;
         i += gridDim.x * blockDim.x) {
        float v = src[i];
        __nv_bfloat16 h = __float2bfloat16(v);
        hi[i] = h;
        lo[i] = __float2bfloat16(v - __bfloat162float(h));
    }
}

// ============================================================================
// Split-bf16 tensor GEMM: C[4096,1024] = A @ W^T (+bias)
// 128x128 block tile, kc=64, 256 threads (8 warps, 2x4), m16n8k16 bf16 mma.
// c_sel 0/1/2 -> q/k/v head-major split-bf16; 3 -> fp32 dout.
// ============================================================================
#define GEMM_SMEM 65536

__global__ __launch_bounds__(256, 1)
void gemm_bf16(int a_sel, int w_idx, const float* __restrict__ bias,
               float* __restrict__ dout, int c_sel)
{
    extern __shared__ char sm[];
    char* sAh = sm;
    char* sAl = sm + 16384;
    char* sWh = sm + 32768;
    char* sWl = sm + 49152;

    const __nv_bfloat16* Ah = a_sel ? g_oh : g_xh;
    const __nv_bfloat16* Al = a_sel ? g_ol : g_xl;
    const __nv_bfloat16* Wh = g_wh + (size_t)w_idx * DMODEL * DMODEL;
    const __nv_bfloat16* Wl = g_wl + (size_t)w_idx * DMODEL * DMODEL;

    const int tid = threadIdx.x;
    const int lane = tid & 31, wid = tid >> 5;
    const int g = lane >> 2, tg = lane & 3;
    const int wm = wid >> 2, wn = wid & 3;
    const int m0 = blockIdx.y * 128, n0 = blockIdx.x * 128;

    float c[4][4][4];
    #pragma unroll
    for (int i = 0; i < 4; i++)
        #pragma unroll
        for (int j = 0; j < 4; j++)
            #pragma unroll
            for (int e = 0; e < 4; e++) c[i][j][e] = 0.f;

    for (int k0 = 0; k0 < DMODEL; k0 += 64) {
        __syncthreads();
        #pragma unroll
        for (int p = 0; p < 4; p++) {
            int idx = p * 256 + tid;
            int r = idx >> 3, ch = idx & 7;
            size_t ga = (size_t)(m0 + r) * DMODEL + k0 + ch * 8;
            size_t gw = (size_t)(n0 + r) * DMODEL + k0 + ch * 8;
            *(uint4*)(sAh + sw128B(r, ch)) = *(const uint4*)(Ah + ga);
            *(uint4*)(sAl + sw128B(r, ch)) = *(const uint4*)(Al + ga);
            *(uint4*)(sWh + sw128B(r, ch)) = *(const uint4*)(Wh + gw);
            *(uint4*)(sWl + sw128B(r, ch)) = *(const uint4*)(Wl + gw);
        }
        __syncthreads();

        #pragma unroll
        for (int kt = 0; kt < 4; kt++) {
            uint32_t ah[4][4], al[4][4];
            const int ar = (lane & 8) + (lane & 7);
            const int ac = kt * 2 + (lane >> 4);
            #pragma unroll
            for (int mi = 0; mi < 4; mi++) {
                int r = wm * 64 + mi * 16 + ar;
                ldsm4(sptr(sAh + sw128B(r, ac)), ah[mi][0], ah[mi][1], ah[mi][2], ah[mi][3]);
                ldsm4(sptr(sAl + sw128B(r, ac)), al[mi][0], al[mi][1], al[mi][2], al[mi][3]);
            }
            uint32_t bh[2][4], bl[2][4];
            const int br = ((lane >> 4) << 3) + (lane & 7);
            const int bc = kt * 2 + ((lane >> 3) & 1);
            #pragma unroll
            for (int pr = 0; pr < 2; pr++) {
                int r = wn * 32 + pr * 16 + br;
                ldsm4(sptr(sWh + sw128B(r, bc)), bh[pr][0], bh[pr][1], bh[pr][2], bh[pr][3]);
                ldsm4(sptr(sWl + sw128B(r, bc)), bl[pr][0], bl[pr][1], bl[pr][2], bl[pr][3]);
            }
            #pragma unroll
            for (int mi = 0; mi < 4; mi++)
                #pragma unroll
                for (int ni = 0; ni < 4; ni++) {
                    uint32_t b0h = bh[ni >> 1][(ni & 1) * 2], b1h = bh[ni >> 1][(ni & 1) * 2 + 1];
                    uint32_t b0l = bl[ni >> 1][(ni & 1) * 2], b1l = bl[ni >> 1][(ni & 1) * 2 + 1];
                    mma16816(c[mi][ni], ah[mi], b0h, b1h);
                    mma16816(c[mi][ni], ah[mi], b0l, b1l);
                    mma16816(c[mi][ni], al[mi], b0h, b1h);
                }
        }
    }

    // epilogue
    __nv_bfloat16 *dsth = nullptr, *dstl = nullptr;
    if (c_sel == 0) { dsth = g_qh; dstl = g_ql; }
    else if (c_sel == 1) { dsth = g_kh; dstl = g_kl; }
    else if (c_sel == 2) { dsth = g_vh; dstl = g_vl; }

    #pragma unroll
    for (int mi = 0; mi < 4; mi++)
        #pragma unroll
        for (int ni = 0; ni < 4; ni++)
            #pragma unroll
            for (int inst = 0; inst < 2; inst++) {
                int m = m0 + wm * 64 + mi * 16 + inst * 8 + g;
                int n = n0 + wn * 32 + ni * 8 + 2 * tg;
                float b0 = bias ? bias[n] : 0.f;
                float b1 = bias ? bias[n + 1] : 0.f;
                float v0 = c[mi][ni][inst * 2] + b0;
                float v1 = c[mi][ni][inst * 2 + 1] + b1;
                if (c_sel < 3) {
                    uint32_t ph, pl;
                    split2(v0, v1, ph, pl);
                    size_t addr = ((size_t)(n >> 6) * TLEN + m) * HDIM + (n & 63);
                    *(uint32_t*)(dsth + addr) = ph;
                    *(uint32_t*)(dstl + addr) = pl;
                } else {
                    float2 r; r.x = v0; r.y = v1;
                    *(float2*)(dout + (size_t)m * DMODEL + n) = r;
                }
            }
}

// ============================================================================
// Tensor-core two-pass attention. Per (head, 128-query block), 256 threads.
// Pass 1: rowmax of scaled scores. Pass 2: recompute, fastexp, split-E, PV.
// ============================================================================
#define ATTN_SMEM 166912

__global__ __launch_bounds__(256, 1)
void attn_kernel(float scaling)
{
    extern __shared__ char sm[];
    char* sQh = sm;
    char* sQl = sm + 16384;
    char* sKh = sm + 32768;
    char* sKl = sm + 49152;
    char* sVh = sm + 65536;
    char* sVl = sm + 81920;
    char* sEh = sm + 98304;
    char* sEl = sm + 131072;
    float* red    = (float*)(sm + 163840);          // [4][128]
    float* rowmax = (float*)(sm + 163840 + 2048);   // [128]
    float* rowsum = rowmax + 128;                   // [128]

    const int tid = threadIdx.x;
    const int lane = tid & 31, wid = tid >> 5;
    const int g = lane >> 2, tg = lane & 3;
    const int wm = wid >> 2, wn = wid & 3;
    const int h = blockIdx.y;
    const int t0 = blockIdx.x * 128;

    const __nv_bfloat16* Qh = g_qh + ((size_t)h * TLEN + t0) * HDIM;
    const __nv_bfloat16* Qlp = g_ql + ((size_t)h * TLEN + t0) * HDIM;
    const __nv_bfloat16* Kh = g_kh + (size_t)h * TLEN * HDIM;
    const __nv_bfloat16* Klp = g_kl + (size_t)h * TLEN * HDIM;
    const __nv_bfloat16* Vh = g_vh + (size_t)h * TLEN * HDIM;
    const __nv_bfloat16* Vlp = g_vl + (size_t)h * TLEN * HDIM;

    // ---- load Q tile ----
    #pragma unroll
    for (int p = 0; p < 4; p++) {
        int idx = p * 256 + tid;
        int r = idx >> 3, ch = idx & 7;
        size_t go = (size_t)r * HDIM + ch * 8;
        *(uint4*)(sQh + sw128B(r, ch)) = *(const uint4*)(Qh + go);
        *(uint4*)(sQl + sw128B(r, ch)) = *(const uint4*)(Qlp + go);
    }

    float rmax[4][2];
    #pragma unroll
    for (int i = 0; i < 4; i++) { rmax[i][0] = -3.402823466e38f; rmax[i][1] = -3.402823466e38f; }

    const int ar = (lane & 8) + (lane & 7);
    const int br = ((lane >> 4) << 3) + (lane & 7);

    // ======================= pass 1: row max =======================
    for (int st = 0; st < TLEN / 128; st++) {
        __syncthreads();
        #pragma unroll
        for (int p = 0; p < 4; p++) {
            int idx = p * 256 + tid;
            int r = idx >> 3, ch = idx & 7;
            size_t go = (size_t)(st * 128 + r) * HDIM + ch * 8;
            *(uint4*)(sKh + sw128B(r, ch)) = *(const uint4*)(Kh + go);
            *(uint4*)(sKl + sw128B(r, ch)) = *(const uint4*)(Klp + go);
        }
        __syncthreads();

        float c[4][4][4];
        #pragma unroll
        for (int i = 0; i < 4; i++)
            #pragma unroll
            for (int j = 0; j < 4; j++)
                #pragma unroll
                for (int e = 0; e < 4; e++) c[i][j][e] = 0.f;

        #pragma unroll
        for (int kt = 0; kt < 4; kt++) {
            uint32_t ah[4][4], al[4][4];
            const int ac = kt * 2 + (lane >> 4);
            #pragma unroll
            for (int mi = 0; mi < 4; mi++) {
                int r = wm * 64 + mi * 16 + ar;
                ldsm4(sptr(sQh + sw128B(r, ac)), ah[mi][0], ah[mi][1], ah[mi][2], ah[mi][3]);
                ldsm4(sptr(sQl + sw128B(r, ac)), al[mi][0], al[mi][1], al[mi][2], al[mi][3]);
            }
            uint32_t bh[2][4], bl[2][4];
            const int bc = kt * 2 + ((lane >> 3) & 1);
            #pragma unroll
            for (int pr = 0; pr < 2; pr++) {
                int r = wn * 32 + pr * 16 + br;
                ldsm4(sptr(sKh + sw128B(r, bc)), bh[pr][0], bh[pr][1], bh[pr][2], bh[pr][3]);
                ldsm4(sptr(sKl + sw128B(r, bc)), bl[pr][0], bl[pr][1], bl[pr][2], bl[pr][3]);
            }
            #pragma unroll
            for (int mi = 0; mi < 4; mi++)
                #pragma unroll
                for (int ni = 0; ni < 4; ni++) {
                    uint32_t b0h = bh[ni >> 1][(ni & 1) * 2], b1h = bh[ni >> 1][(ni & 1) * 2 + 1];
                    uint32_t b0l = bl[ni >> 1][(ni & 1) * 2], b1l = bl[ni >> 1][(ni & 1) * 2 + 1];
                    mma16816(c[mi][ni], ah[mi], b0h, b1h);
                    mma16816(c[mi][ni], ah[mi], b0l, b1l);
                    mma16816(c[mi][ni], al[mi], b0h, b1h);
                }
        }
        #pragma unroll
        for (int mi = 0; mi < 4; mi++)
            #pragma unroll
            for (int ni = 0; ni < 4; ni++)
                #pragma unroll
                for (int e = 0; e < 4; e++)
                    rmax[mi][e >> 1] = fmaxf(rmax[mi][e >> 1], __fmul_rn(c[mi][ni][e], scaling));
    }

    // ---- cross-lane/warp rowmax reduce ----
    #pragma unroll
    for (int mi = 0; mi < 4; mi++)
        #pragma unroll
        for (int inst = 0; inst < 2; inst++) {
            float v = rmax[mi][inst];
            v = fmaxf(v, __shfl_xor_sync(0xffffffff, v, 1));
            v = fmaxf(v, __shfl_xor_sync(0xffffffff, v, 2));
            if (tg == 0) red[wn * 128 + wm * 64 + mi * 16 + inst * 8 + g] = v;
        }
    __syncthreads();
    if (tid < 128) {
        float v = red[tid];
        v = fmaxf(v, red[128 + tid]);
        v = fmaxf(v, red[256 + tid]);
        v = fmaxf(v, red[384 + tid]);
        rowmax[tid] = v;
    }
    __syncthreads();
    float rm[4][2];
    #pragma unroll
    for (int mi = 0; mi < 4; mi++)
        #pragma unroll
        for (int inst = 0; inst < 2; inst++)
            rm[mi][inst] = rowmax[wm * 64 + mi * 16 + inst * 8 + g];

    float o[4][2][4];
    #pragma unroll
    for (int i = 0; i < 4; i++)
        #pragma unroll
        for (int j = 0; j < 2; j++)
            #pragma unroll
            for (int e = 0; e < 4; e++) o[i][j][e] = 0.f;
    float rs[4][2];
    #pragma unroll
    for (int i = 0; i < 4; i++) { rs[i][0] = 0.f; rs[i][1] = 0.f; }

    // ======================= pass 2 =======================
    for (int st = 0; st < TLEN / 128; st++) {
        __syncthreads();
        #pragma unroll
        for (int p = 0; p < 4; p++) {
            int idx = p * 256 + tid;
            int r = idx >> 3, ch = idx & 7;
            size_t go = (size_t)(st * 128 + r) * HDIM + ch * 8;
            *(uint4*)(sKh + sw128B(r, ch)) = *(const uint4*)(Kh + go);
            *(uint4*)(sKl + sw128B(r, ch)) = *(const uint4*)(Klp + go);
            *(uint4*)(sVh + sw128B(r, ch)) = *(const uint4*)(Vh + go);
            *(uint4*)(sVl + sw128B(r, ch)) = *(const uint4*)(Vlp + go);
        }
        __syncthreads();

        float c[4][4][4];
        #pragma unroll
        for (int i = 0; i < 4; i++)
            #pragma unroll
            for (int j = 0; j < 4; j++)
                #pragma unroll
                for (int e = 0; e < 4; e++) c[i][j][e] = 0.f;

        #pragma unroll
        for (int kt = 0; kt < 4; kt++) {
            uint32_t ah[4][4], al[4][4];
            const int ac = kt * 2 + (lane >> 4);
            #pragma unroll
            for (int mi = 0; mi < 4; mi++) {
                int r = wm * 64 + mi * 16 + ar;
                ldsm4(sptr(sQh + sw128B(r, ac)), ah[mi][0], ah[mi][1], ah[mi][2], ah[mi][3]);
                ldsm4(sptr(sQl + sw128B(r, ac)), al[mi][0], al[mi][1], al[mi][2], al[mi][3]);
            }
            uint32_t bh[2][4], bl[2][4];
            const int bc = kt * 2 + ((lane >> 3) & 1);
            #pragma unroll
            for (int pr = 0; pr < 2; pr++) {
                int r = wn * 32 + pr * 16 + br;
                ldsm4(sptr(sKh + sw128B(r, bc)), bh[pr][0], bh[pr][1], bh[pr][2], bh[pr][3]);
                ldsm4(sptr(sKl + sw128B(r, bc)), bl[pr][0], bl[pr][1], bl[pr][2], bl[pr][3]);
            }
            #pragma unroll
            for (int mi = 0; mi < 4; mi++)
                #pragma unroll
                for (int ni = 0; ni < 4; ni++) {
                    uint32_t b0h = bh[ni >> 1][(ni & 1) * 2], b1h = bh[ni >> 1][(ni & 1) * 2 + 1];
                    uint32_t b0l = bl[ni >> 1][(ni & 1) * 2], b1l = bl[ni >> 1][(ni & 1) * 2 + 1];
                    mma16816(c[mi][ni], ah[mi], b0h, b1h);
                    mma16816(c[mi][ni], ah[mi], b0l, b1l);
                    mma16816(c[mi][ni], al[mi], b0h, b1h);
                }
        }

        // exp + split E into SMEM
        #pragma unroll
        for (int mi = 0; mi < 4; mi++)
            #pragma unroll
            for (int ni = 0; ni < 4; ni++)
                #pragma unroll
                for (int inst = 0; inst < 2; inst++) {
                    float e0 = fastexp_g(__fmul_rn(c[mi][ni][inst * 2], scaling) - rm[mi][inst]);
                    float e1 = fastexp_g(__fmul_rn(c[mi][ni][inst * 2 + 1], scaling) - rm[mi][inst]);
                    rs[mi][inst] += e0;
                    rs[mi][inst] += e1;
                    uint32_t ph, pl;
                    split2(e0, e1, ph, pl);
                    int r = wm * 64 + mi * 16 + inst * 8 + g;
                    int col = wn * 32 + ni * 8 + 2 * tg;
                    int byt = sw256B(r, col >> 3) + (col & 7) * 2;
                    *(uint32_t*)(sEh + byt) = ph;
                    *(uint32_t*)(sEl + byt) = pl;
                }
        __syncthreads();

        // PV: O += E @ V
        #pragma unroll
        for (int kt = 0; kt < 8; kt++) {
            uint32_t eh[4][4], el[4][4];
            const int ac = kt * 2 + (lane >> 4);
            #pragma unroll
            for (int mi = 0; mi < 4; mi++) {
                int r = wm * 64 + mi * 16 + ar;
                ldsm4(sptr(sEh + sw256B(r, ac)), eh[mi][0], eh[mi][1], eh[mi][2], eh[mi][3]);
                ldsm4(sptr(sEl + sw256B(r, ac)), el[mi][0], el[mi][1], el[mi][2], el[mi][3]);
            }
            uint32_t vh[4], vl[4];
            int vr = kt * 16 + (lane & 8) + (lane & 7);
            int vc = wn * 2 + (lane >> 4);
            ldsm4t(sptr(sVh + sw128B(vr, vc)), vh[0], vh[1], vh[2], vh[3]);
            ldsm4t(sptr(sVl + sw128B(vr, vc)), vl[0], vl[1], vl[2], vl[3]);
            #pragma unroll
            for (int mi = 0; mi < 4; mi++)
                #pragma unroll
                for (int ni2 = 0; ni2 < 2; ni2++) {
                    mma16816(o[mi][ni2], eh[mi], vh[ni2 * 2], vh[ni2 * 2 + 1]);
                    mma16816(o[mi][ni2], eh[mi], vl[ni2 * 2], vl[ni2 * 2 + 1]);
                    mma16816(o[mi][ni2], el[mi], vh[ni2 * 2], vh[ni2 * 2 + 1]);
                }
        }
    }

    // ---- rowsum reduce ----
    #pragma unroll
    for (int mi = 0; mi < 4; mi++)
        #pragma unroll
        for (int inst = 0; inst < 2; inst++) {
            float v = rs[mi][inst];
            v += __shfl_xor_sync(0xffffffff, v, 1);
            v += __shfl_xor_sync(0xffffffff, v, 2);
            if (tg == 0) red[wn * 128 + wm * 64 + mi * 16 + inst * 8 + g] = v;
        }
    __syncthreads();
    if (tid < 128)
        rowsum[tid] = red[tid] + red[128 + tid] + red[256 + tid] + red[384 + tid];
    __syncthreads();

    // ---- normalize + split-store O ----
    #pragma unroll
    for (int mi = 0; mi < 4; mi++)
        #pragma unroll
        for (int inst = 0; inst < 2; inst++) {
            int r = wm * 64 + mi * 16 + inst * 8 + g;
            float inv = 1.0f / rowsum[r];
            #pragma unroll
            for (int ni2 = 0; ni2 < 2; ni2++) {
                float v0 = o[mi][ni2][inst * 2] * inv;
                float v1 = o[mi][ni2][inst * 2 + 1] * inv;
                uint32_t ph, pl;
                split2(v0, v1, ph, pl);
                int d = wn * 16 + ni2 * 8 + 2 * tg;
                size_t addr = (size_t)(t0 + r) * DMODEL + h * HDIM + d;
                *(uint32_t*)(g_oh + addr) = ph;
                *(uint32_t*)(g_ol + addr) = pl;
            }
        }
}

// ============================================================================
extern "C" void kernel_launch(void* const* d_in, const int* in_sizes, int n_in,
                              void* d_out, int out_size)
{
    const float* x  = (const float*)d_in[0];
    const float* Wq = (const float*)d_in[1];
    const float* bq = (const float*)d_in[2];
    const float* Wk = (const float*)d_in[3];
    const float* bk = (const float*)d_in[4];
    const float* Wv = (const float*)d_in[5];
    const float* bv = (const float*)d_in[6];
    const float* Wo = (const float*)d_in[7];
    float* out = (float*)d_out;

    // Quake q_rsqrt(HEAD_DIM=64) exact fp32 step order
    float xq = 64.0f;
    int ib;
    memcpy(&ib, &xq, 4);
    ib = 0x5f3759df - (ib >> 1);
    float y;
    memcpy(&y, &ib, 4);
    float t = 0.5f * xq;
    t = t * y;
    t = t * y;
    float scaling = y * (1.5f - t);

    cudaFuncSetAttribute(attn_kernel, cudaFuncAttributeMaxDynamicSharedMemorySize, ATTN_SMEM);
    cudaFuncSetAttribute(gemm_bf16, cudaFuncAttributeMaxDynamicSharedMemorySize, GEMM_SMEM);

    split_kernel<<<2048, 256>>>(x,  0, TLEN * DMODEL);
    split_kernel<<<1024, 256>>>(Wq, 1, DMODEL * DMODEL);
    split_kernel<<<1024, 256>>>(Wk, 2, DMODEL * DMODEL);
    split_kernel<<<1024, 256>>>(Wv, 3, DMODEL * DMODEL);
    split_kernel<<<1024, 256>>>(Wo, 4, DMODEL * DMODEL);

    dim3 pgrid(DMODEL / 128, TLEN / 128);
    gemm_bf16<<<pgrid, 256, GEMM_SMEM>>>(0, 0, bq, out, 0);
    gemm_bf16<<<pgrid, 256, GEMM_SMEM>>>(0, 1, bk, out, 1);
    gemm_bf16<<<pgrid, 256, GEMM_SMEM>>>(0, 2, bv, out, 2);

    attn_kernel<<<dim3(TLEN / 128, NHEADS), 256, ATTN_SMEM>>>(scaling);

    gemm_bf16<<<pgrid, 256, GEMM_SMEM>>>(1, 3, nullptr, out, 3);
}